// round 15
// baseline (speedup 1.0000x reference)
#include <cuda_runtime.h>
#include <cuda_bf16.h>
#include <math.h>

#define B_   256
#define A_   64
#define G_   978
#define DDRUG 128
#define DCELL 50
#define CELLIN 978
#define DOSEIN 12
#define GLOBAL_ 306   // 128+50+128
#define EXPIN 434
#define E_   4
#define H_   128

#define NCHUNK 16     // k-split for cell L1
#define GT    36      // combine gene tile (36*128*16B = 72KB dynamic smem)

// -------- device scratch --------
__device__ float d_gfeat[B_ * GLOBAL_];
__device__ float d_c1p[NCHUNK * B_ * 200];  // cell L1 partials [chunk][row][200]
__device__ float d_d1[B_ * 64];
__device__ __align__(16) float d_U[B_ * E_ * H_];   // [b][e*128+h]
__device__ __align__(16) float d_V[G_ * E_ * H_];   // [g][e*128+h]
__device__ int   d_eidx[B_ * 2];
__device__ float d_gw[B_ * 2];
__device__ float d_biasc[B_];

// =========================================================
// Stage A (inputs only), 256 threads, grid 828:
//   [0,128)    drug atom-sum, 2 rows/block
//   [128,640)  cell L1 partials: 16 k-chunks x 32 row-tiles (RB=8)
//   [640,704)  dose L1: 4 rows/block
//   [704,828)  V = gene_emb @ eW1[:,306:,:]: 62 tiles(16) x 2 expert-pairs
// =========================================================
__global__ void __launch_bounds__(256) stageA(
    const float* __restrict__ drug,
    const float* __restrict__ gex,
    const float* __restrict__ cW1,
    const float* __restrict__ idose,
    const float* __restrict__ dW1, const float* __restrict__ db1,
    const float* __restrict__ gene_emb,
    const float* __restrict__ eW1)
{
    __shared__ __align__(16) float sA[16 * 128];
    const int blk = blockIdx.x;
    const int t = threadIdx.x;

    if (blk < 128) {
        int b = blk * 2 + (t >> 7);
        int d = t & 127;
        const float* p = drug + (size_t)b * A_ * DDRUG + d;
        float s = 0.f;
#pragma unroll
        for (int a = 0; a < A_; a++) s += p[a * DDRUG];
        d_gfeat[b * GLOBAL_ + d] = s;

    } else if (blk < 640) {
        // ---- cell L1 partial: chunk c (of 16), rows r0..r0+7 ----
        int idx = blk - 128;
        int c = idx >> 5, rt = idx & 31;
        int r0 = rt * 8;
        int k0 = (CELLIN * c) / NCHUNK;
        int k1 = (CELLIN * (c + 1)) / NCHUNK;
        int kc = k1 - k0;                 // 61 or 62
        const int Kp = 64;
        for (int i = t; i < 8 * Kp; i += 256) {
            int r = i >> 6, k = i & 63;
            sA[i] = (k < kc) ? gex[(r0 + r) * CELLIN + k0 + k] : 0.f;
        }
        __syncthreads();
        if (t < 200) {
            float acc[8];
#pragma unroll
            for (int r = 0; r < 8; r++) acc[r] = 0.f;
            int k = 0;
            for (; k + 8 <= kc; k += 8) {
                float w[8];
#pragma unroll
                for (int j = 0; j < 8; j++)
                    w[j] = cW1[(k0 + k + j) * 200 + t];
#pragma unroll
                for (int r = 0; r < 8; r++) {
                    float4 xa = *reinterpret_cast<const float4*>(sA + r * Kp + k);
                    float4 xb = *reinterpret_cast<const float4*>(sA + r * Kp + k + 4);
                    acc[r] = fmaf(xa.x, w[0], acc[r]);
                    acc[r] = fmaf(xa.y, w[1], acc[r]);
                    acc[r] = fmaf(xa.z, w[2], acc[r]);
                    acc[r] = fmaf(xa.w, w[3], acc[r]);
                    acc[r] = fmaf(xb.x, w[4], acc[r]);
                    acc[r] = fmaf(xb.y, w[5], acc[r]);
                    acc[r] = fmaf(xb.z, w[6], acc[r]);
                    acc[r] = fmaf(xb.w, w[7], acc[r]);
                }
            }
            for (; k < kc; k++) {
                float w = cW1[(k0 + k) * 200 + t];
#pragma unroll
                for (int r = 0; r < 8; r++)
                    acc[r] = fmaf(sA[r * Kp + k], w, acc[r]);
            }
#pragma unroll
            for (int r = 0; r < 8; r++)
                d_c1p[(c * B_ + r0 + r) * 200 + t] = acc[r];
        }

    } else if (blk < 704) {
        int row = (blk - 640) * 4 + (t >> 6);
        int col = t & 63;
        float a = db1[col];
        const float* x = idose + row * DOSEIN;
#pragma unroll
        for (int k = 0; k < DOSEIN; k++)
            a = fmaf(x[k], dW1[k * 64 + col], a);
        d_d1[row * 64 + col] = fmaxf(a, 0.f);

    } else {
        // ---- V: 16 genes x 2 experts per block ----
        int idx = blk - 704;             // 0..123
        int rt = idx >> 1, ep = idx & 1;
        int r0 = rt * 16;
        int e = ep * 2 + (t >> 7), h = t & 127;
        for (int i = t; i < 16 * 128; i += 256) {
            int r = i >> 7, k = i & 127;
            sA[i] = (r0 + r < G_) ? gene_emb[(r0 + r) * 128 + k] : 0.f;
        }
        __syncthreads();
        float acc[16];
#pragma unroll
        for (int r = 0; r < 16; r++) acc[r] = 0.f;
        const float* Wv = eW1 + (size_t)e * EXPIN * H_ + (size_t)GLOBAL_ * H_ + h;
#pragma unroll 1
        for (int k = 0; k < 128; k += 8) {
            float w[8];
#pragma unroll
            for (int j = 0; j < 8; j++)
                w[j] = Wv[(k + j) * H_];
#pragma unroll
            for (int r = 0; r < 16; r++) {
                float4 xa = *reinterpret_cast<const float4*>(sA + r * 128 + k);
                float4 xb = *reinterpret_cast<const float4*>(sA + r * 128 + k + 4);
                acc[r] = fmaf(xa.x, w[0], acc[r]);
                acc[r] = fmaf(xa.y, w[1], acc[r]);
                acc[r] = fmaf(xa.z, w[2], acc[r]);
                acc[r] = fmaf(xa.w, w[3], acc[r]);
                acc[r] = fmaf(xb.x, w[4], acc[r]);
                acc[r] = fmaf(xb.y, w[5], acc[r]);
                acc[r] = fmaf(xb.z, w[6], acc[r]);
                acc[r] = fmaf(xb.w, w[7], acc[r]);
            }
        }
#pragma unroll
        for (int r = 0; r < 16; r++)
            if (r0 + r < G_) d_V[(r0 + r) * (E_ * H_) + e * H_ + h] = acc[r];
    }
}

// =========================================================
// Stage BC, 256 threads, 2 rows/block:
//   [0,128)   cell L2+L3 fused
//   [128,256) dose L2
// Fires PDL trigger at start: any BC block running implies stageA is
// complete (BC has a full stream dependency on A), so DE's pre-sync
// prefetch of A-produced data is safe.
// =========================================================
__global__ void __launch_bounds__(256) stageBC(
    const float* __restrict__ cb1,
    const float* __restrict__ cW2, const float* __restrict__ cb2,
    const float* __restrict__ cW3, const float* __restrict__ cb3,
    const float* __restrict__ dW2, const float* __restrict__ db2,
    float* __restrict__ cellOut)
{
#if __CUDA_ARCH__ >= 900
    cudaTriggerProgrammaticLaunchCompletion();
#endif
    __shared__ __align__(16) float sA[2 * 200];
    __shared__ __align__(16) float sH[2 * 100];
    const int blk = blockIdx.x;
    const int t = threadIdx.x;

    if (blk < 128) {
        int r0 = blk * 2;
        for (int i = t; i < 2 * 200; i += 256) {
            int r = i / 200, k = i - r * 200;
            float s = cb1[k];
#pragma unroll
            for (int c = 0; c < NCHUNK; c++)
                s += d_c1p[(c * B_ + r0 + r) * 200 + k];
            sA[i] = fmaxf(s, 0.f);
        }
        __syncthreads();
        if (t < 100) {
            float acc[2];
#pragma unroll
            for (int r = 0; r < 2; r++) acc[r] = cb2[t];
            for (int k = 0; k < 200; k += 8) {
                float w[8];
#pragma unroll
                for (int j = 0; j < 8; j++)
                    w[j] = cW2[(k + j) * 100 + t];
#pragma unroll
                for (int r = 0; r < 2; r++) {
                    float4 xa = *reinterpret_cast<const float4*>(sA + r * 200 + k);
                    float4 xb = *reinterpret_cast<const float4*>(sA + r * 200 + k + 4);
                    acc[r] = fmaf(xa.x, w[0], acc[r]);
                    acc[r] = fmaf(xa.y, w[1], acc[r]);
                    acc[r] = fmaf(xa.z, w[2], acc[r]);
                    acc[r] = fmaf(xa.w, w[3], acc[r]);
                    acc[r] = fmaf(xb.x, w[4], acc[r]);
                    acc[r] = fmaf(xb.y, w[5], acc[r]);
                    acc[r] = fmaf(xb.z, w[6], acc[r]);
                    acc[r] = fmaf(xb.w, w[7], acc[r]);
                }
            }
#pragma unroll
            for (int r = 0; r < 2; r++)
                sH[r * 100 + t] = fmaxf(acc[r], 0.f);
        }
        __syncthreads();
        if (t < 50) {
            float acc[2];
#pragma unroll
            for (int r = 0; r < 2; r++) acc[r] = cb3[t];
            for (int k = 0; k < 100; k += 4) {
                float w0 = cW3[(k + 0) * 50 + t];
                float w1 = cW3[(k + 1) * 50 + t];
                float w2 = cW3[(k + 2) * 50 + t];
                float w3 = cW3[(k + 3) * 50 + t];
#pragma unroll
                for (int r = 0; r < 2; r++) {
                    float4 x = *reinterpret_cast<const float4*>(sH + r * 100 + k);
                    acc[r] = fmaf(x.x, w0, acc[r]);
                    acc[r] = fmaf(x.y, w1, acc[r]);
                    acc[r] = fmaf(x.z, w2, acc[r]);
                    acc[r] = fmaf(x.w, w3, acc[r]);
                }
            }
#pragma unroll
            for (int r = 0; r < 2; r++) {
                float v = fmaxf(acc[r], 0.f);
                d_gfeat[(r0 + r) * GLOBAL_ + 128 + t] = v;
                if (cellOut) cellOut[(r0 + r) * DCELL + t] = v;
            }
        }
    } else {
        int r0 = (blk - 128) * 2;
        for (int i = t; i < 2 * 64; i += 256) {
            int r = i >> 6, k = i & 63;
            sA[i] = d_d1[(r0 + r) * 64 + k];
        }
        __syncthreads();
        if (t < 128) {
            float acc[2];
#pragma unroll
            for (int r = 0; r < 2; r++) acc[r] = db2[t];
            for (int k = 0; k < 64; k += 8) {
                float w[8];
#pragma unroll
                for (int j = 0; j < 8; j++)
                    w[j] = dW2[(k + j) * 128 + t];
#pragma unroll
                for (int r = 0; r < 2; r++) {
                    float4 xa = *reinterpret_cast<const float4*>(sA + r * 64 + k);
                    float4 xb = *reinterpret_cast<const float4*>(sA + r * 64 + k + 4);
                    acc[r] = fmaf(xa.x, w[0], acc[r]);
                    acc[r] = fmaf(xa.y, w[1], acc[r]);
                    acc[r] = fmaf(xa.z, w[2], acc[r]);
                    acc[r] = fmaf(xa.w, w[3], acc[r]);
                    acc[r] = fmaf(xb.x, w[4], acc[r]);
                    acc[r] = fmaf(xb.y, w[5], acc[r]);
                    acc[r] = fmaf(xb.z, w[6], acc[r]);
                    acc[r] = fmaf(xb.w, w[7], acc[r]);
                }
            }
#pragma unroll
            for (int r = 0; r < 2; r++)
                d_gfeat[(r0 + r) * GLOBAL_ + 178 + t] = fmaxf(acc[r], 0.f);
        }
    }
}

// =========================================================
// Stage DE, 256 threads, grid 384 (PSS after BC):
//   [0,128)   gating: 2 rows/block
//   [128,384) U: 2 rows x 2 experts per block
// Pre-sync: prefetch drug cols [0,128) of gfeat (stageA-produced — safe
// because DE blocks only exist after BC blocks started, implying A done).
// Then gridsync, then load BC-produced cols [128,306).
// Triggers early so combine's V-prefetch overlaps DE.
// =========================================================
__global__ void __launch_bounds__(256) stageDE(
    const float* __restrict__ gW1, const float* __restrict__ gb1,
    const float* __restrict__ gW2, const float* __restrict__ gb2,
    const float* __restrict__ eW1, const float* __restrict__ eb1,
    const float* __restrict__ eb2)
{
#if __CUDA_ARCH__ >= 900
    cudaTriggerProgrammaticLaunchCompletion();
#endif
    __shared__ __align__(16) float sG[2 * 308];
    const int blk = blockIdx.x;
    const int t = threadIdx.x;
    const bool isGate = (blk < 128);
    const int r0 = isGate ? blk * 2 : ((blk - 128) >> 1) * 2;

    // pre-sync: drug columns [0,128) — produced by stageA
    for (int i = t; i < 2 * 128; i += 256) {
        int r = i >> 7, k = i & 127;
        sG[r * 308 + k] = d_gfeat[(r0 + r) * GLOBAL_ + k];
    }

#if __CUDA_ARCH__ >= 900
    cudaGridDependencySynchronize();     // wait for stageBC outputs
#endif

    // post-sync: cols [128,308) (cell+dose; pad 306..307 with 0)
    for (int i = t; i < 2 * 180; i += 256) {
        int r = i / 180, k = 128 + (i - r * 180);
        sG[r * 308 + k] = (k < GLOBAL_) ? d_gfeat[(r0 + r) * GLOBAL_ + k] : 0.f;
    }
    __syncthreads();

    if (isGate) {
        __shared__ float sHp[2][2][128];
        __shared__ float sH[2 * 128];
        __shared__ float sL[8];
        int b0 = r0;
        {
            int half = t >> 7, h = t & 127;
            float acc[2] = {0.f, 0.f};
            int kA = half ? 152 : 0;
            int kE = half ? 304 : 152;
            for (int k = kA; k < kE; k += 8) {
                float w[8];
#pragma unroll
                for (int j = 0; j < 8; j++)
                    w[j] = gW1[(k + j) * 128 + h];
#pragma unroll
                for (int r = 0; r < 2; r++) {
                    float4 xa = *reinterpret_cast<const float4*>(sG + r * 308 + k);
                    float4 xb = *reinterpret_cast<const float4*>(sG + r * 308 + k + 4);
                    acc[r] = fmaf(xa.x, w[0], acc[r]);
                    acc[r] = fmaf(xa.y, w[1], acc[r]);
                    acc[r] = fmaf(xa.z, w[2], acc[r]);
                    acc[r] = fmaf(xa.w, w[3], acc[r]);
                    acc[r] = fmaf(xb.x, w[4], acc[r]);
                    acc[r] = fmaf(xb.y, w[5], acc[r]);
                    acc[r] = fmaf(xb.z, w[6], acc[r]);
                    acc[r] = fmaf(xb.w, w[7], acc[r]);
                }
            }
            if (half) {
                for (int k = 304; k < GLOBAL_; k++) {
                    float w = gW1[k * 128 + h];
#pragma unroll
                    for (int r = 0; r < 2; r++)
                        acc[r] = fmaf(sG[r * 308 + k], w, acc[r]);
                }
            }
#pragma unroll
            for (int r = 0; r < 2; r++) sHp[half][r][h] = acc[r];
        }
        __syncthreads();
        if (t < 128) {
            float bb = gb1[t];
#pragma unroll
            for (int r = 0; r < 2; r++)
                sH[r * 128 + t] = fmaxf(sHp[0][r][t] + sHp[1][r][t] + bb, 0.f);
        }
        __syncthreads();
        if (t < 8) {
            int r = t >> 2, e = t & 3;
            float a = gb2[e];
            for (int k = 0; k < 128; k++)
                a = fmaf(sH[r * 128 + k], gW2[k * 4 + e], a);
            sL[t] = a;
        }
        __syncthreads();
        if (t < 2) {
            int b = b0 + t;
            float v[4];
#pragma unroll
            for (int j = 0; j < 4; j++) v[j] = sL[t * 4 + j];
            int i0 = 0;
#pragma unroll
            for (int j = 1; j < 4; j++) if (v[j] > v[i0]) i0 = j;
            int i1 = (i0 == 0) ? 1 : 0;
#pragma unroll
            for (int j = 0; j < 4; j++) if (j != i0 && v[j] > v[i1]) i1 = j;
            float m  = fmaxf(v[i0], v[i1]);
            float e0 = __expf(v[i0] - m), e1 = __expf(v[i1] - m);
            float inv = 1.f / (e0 + e1);
            float w0 = e0 * inv, w1 = e1 * inv;
            d_eidx[2 * b]     = i0;
            d_eidx[2 * b + 1] = i1;
            d_gw[2 * b]       = w0;
            d_gw[2 * b + 1]   = w1;
            d_biasc[b]        = w0 * eb2[i0] + w1 * eb2[i1];
        }
    } else {
        // U: 2 rows x 2 experts per block
        int ep = (blk - 128) & 1;
        int e = ep * 2 + (t >> 7), h = t & 127;
        float acc[2];
        float bb = eb1[e * H_ + h];
#pragma unroll
        for (int r = 0; r < 2; r++) acc[r] = bb;
        const float* Wp = eW1 + (size_t)e * EXPIN * H_ + h;
#pragma unroll 1
        for (int k = 0; k < 304; k += 8) {
            float w[8];
#pragma unroll
            for (int j = 0; j < 8; j++)
                w[j] = Wp[(k + j) * H_];
#pragma unroll
            for (int r = 0; r < 2; r++) {
                float4 xa = *reinterpret_cast<const float4*>(sG + r * 308 + k);
                float4 xb = *reinterpret_cast<const float4*>(sG + r * 308 + k + 4);
                acc[r] = fmaf(xa.x, w[0], acc[r]);
                acc[r] = fmaf(xa.y, w[1], acc[r]);
                acc[r] = fmaf(xa.z, w[2], acc[r]);
                acc[r] = fmaf(xa.w, w[3], acc[r]);
                acc[r] = fmaf(xb.x, w[4], acc[r]);
                acc[r] = fmaf(xb.y, w[5], acc[r]);
                acc[r] = fmaf(xb.z, w[6], acc[r]);
                acc[r] = fmaf(xb.w, w[7], acc[r]);
            }
        }
        for (int k = 304; k < GLOBAL_; k++) {
            float w = Wp[k * H_];
#pragma unroll
            for (int r = 0; r < 2; r++)
                acc[r] = fmaf(sG[r * 308 + k], w, acc[r]);
        }
#pragma unroll
        for (int r = 0; r < 2; r++)
            d_U[(r0 + r) * (E_ * H_) + e * H_ + h] = acc[r];
    }
}

// =========================================================
// Combine: warp = one b, 36-gene tile (dynamic smem, single wave),
// paired-gene merged reduce, fully unrolled full-tile path, PDL.
// =========================================================
struct CombCtx {
    const float4* sVbase0;   // sV + e0*32 + lane
    const float4* sVbase1;   // sV + e1*32 + lane
    float4 u0, u1, w20, w21;
    float bc;
    float* outp;             // pred + b*G_ + g0
    int lane;
};

__device__ __forceinline__ void comb_pair(const CombCtx& c, int gi)
{
    float4 va0 = c.sVbase0[(gi + 0) * 128];
    float4 va1 = c.sVbase1[(gi + 0) * 128];
    float4 vb0 = c.sVbase0[(gi + 1) * 128];
    float4 vb1 = c.sVbase1[(gi + 1) * 128];

    float p0 =           fmaxf(c.u0.x + va0.x, 0.f) * c.w20.x;
    p0 = fmaf(fmaxf(c.u0.y + va0.y, 0.f), c.w20.y, p0);
    p0 = fmaf(fmaxf(c.u0.z + va0.z, 0.f), c.w20.z, p0);
    p0 = fmaf(fmaxf(c.u0.w + va0.w, 0.f), c.w20.w, p0);
    p0 = fmaf(fmaxf(c.u1.x + va1.x, 0.f), c.w21.x, p0);
    p0 = fmaf(fmaxf(c.u1.y + va1.y, 0.f), c.w21.y, p0);
    p0 = fmaf(fmaxf(c.u1.z + va1.z, 0.f), c.w21.z, p0);
    p0 = fmaf(fmaxf(c.u1.w + va1.w, 0.f), c.w21.w, p0);

    float p1 =           fmaxf(c.u0.x + vb0.x, 0.f) * c.w20.x;
    p1 = fmaf(fmaxf(c.u0.y + vb0.y, 0.f), c.w20.y, p1);
    p1 = fmaf(fmaxf(c.u0.z + vb0.z, 0.f), c.w20.z, p1);
    p1 = fmaf(fmaxf(c.u0.w + vb0.w, 0.f), c.w20.w, p1);
    p1 = fmaf(fmaxf(c.u1.x + vb1.x, 0.f), c.w21.x, p1);
    p1 = fmaf(fmaxf(c.u1.y + vb1.y, 0.f), c.w21.y, p1);
    p1 = fmaf(fmaxf(c.u1.z + vb1.z, 0.f), c.w21.z, p1);
    p1 = fmaf(fmaxf(c.u1.w + vb1.w, 0.f), c.w21.w, p1);

    float z0 = p0 + __shfl_xor_sync(0xffffffffu, p0, 16);
    float z1 = p1 + __shfl_xor_sync(0xffffffffu, p1, 16);
    float s  = (c.lane & 16) ? z1 : z0;
    s += __shfl_xor_sync(0xffffffffu, s, 8);
    s += __shfl_xor_sync(0xffffffffu, s, 4);
    s += __shfl_xor_sync(0xffffffffu, s, 2);
    s += __shfl_xor_sync(0xffffffffu, s, 1);
    if (c.lane == 0)
        c.outp[gi] = s + c.bc;
    else if (c.lane == 16)
        c.outp[gi + 1] = s + c.bc;
}

__global__ void __launch_bounds__(512) combine_kernel(
    const float* __restrict__ expW2, float* __restrict__ pred)
{
    extern __shared__ float4 sV[];       // GT*128 float4 = 72KB
    const int g0   = blockIdx.x * GT;
    const int warp = threadIdx.x >> 5;
    const int lane = threadIdx.x & 31;
    const int b    = blockIdx.y * 16 + warp;
    const int nG   = (G_ - g0) < GT ? (G_ - g0) : GT;   // 36 or 6 (even)

    // V prefetch — safe pre-sync: d_V written by stageA, complete before
    // our PDL predecessor chain (BC, DE) could have begun.
    const float4* V4 = reinterpret_cast<const float4*>(d_V);
    for (int i = threadIdx.x; i < nG * 128; i += blockDim.x)
        sV[i] = V4[g0 * 128 + i];
    __syncthreads();

#if __CUDA_ARCH__ >= 900
    cudaGridDependencySynchronize();     // wait for stageDE outputs
#endif

    const int   e0  = d_eidx[2 * b], e1 = d_eidx[2 * b + 1];
    const float gw0 = d_gw[2 * b],   gw1 = d_gw[2 * b + 1];

    const float4* U4 = reinterpret_cast<const float4*>(d_U) + b * 128;
    const float4* W4 = reinterpret_cast<const float4*>(expW2);

    CombCtx c;
    c.lane = lane;
    c.bc   = d_biasc[b];
    c.outp = pred + b * G_ + g0;
    c.sVbase0 = sV + e0 * 32 + lane;
    c.sVbase1 = sV + e1 * 32 + lane;
    c.u0 = U4[e0 * 32 + lane];
    c.u1 = U4[e1 * 32 + lane];
    float4 w20 = W4[e0 * 32 + lane];
    w20.x *= gw0; w20.y *= gw0; w20.z *= gw0; w20.w *= gw0;
    float4 w21 = W4[e1 * 32 + lane];
    w21.x *= gw1; w21.y *= gw1; w21.z *= gw1; w21.w *= gw1;
    c.w20 = w20; c.w21 = w21;

    if (nG == GT) {
#pragma unroll
        for (int gi = 0; gi < GT; gi += 2)
            comb_pair(c, gi);
    } else {
#pragma unroll
        for (int gi = 0; gi < 6; gi += 2)     // tail tile: nG = 6
            comb_pair(c, gi);
    }
}

// =========================================================
extern "C" void kernel_launch(void* const* d_in, const int* in_sizes, int n_in,
                              void* d_out, int out_size)
{
    const float* drug_atom = (const float*)d_in[0];
    const float* gex       = (const float*)d_in[1];
    const float* idose     = (const float*)d_in[2];
    const float* cW1 = (const float*)d_in[3];  const float* cb1 = (const float*)d_in[4];
    const float* cW2 = (const float*)d_in[5];  const float* cb2 = (const float*)d_in[6];
    const float* cW3 = (const float*)d_in[7];  const float* cb3 = (const float*)d_in[8];
    const float* dW1 = (const float*)d_in[9];  const float* db1 = (const float*)d_in[10];
    const float* dW2 = (const float*)d_in[11]; const float* db2 = (const float*)d_in[12];
    const float* gene_emb = (const float*)d_in[13];
    const float* gW1 = (const float*)d_in[14]; const float* gb1 = (const float*)d_in[15];
    const float* gW2 = (const float*)d_in[16]; const float* gb2 = (const float*)d_in[17];
    const float* eW1 = (const float*)d_in[18]; const float* eb1 = (const float*)d_in[19];
    const float* eW2 = (const float*)d_in[20]; const float* eb2 = (const float*)d_in[21];

    float* pred = (float*)d_out;
    float* cellOut = (out_size >= B_ * G_ + B_ * DCELL) ? pred + B_ * G_ : nullptr;

    stageA<<<828, 256>>>(drug_atom, gex, cW1, idose, dW1, db1, gene_emb, eW1);
    stageBC<<<256, 256>>>(cb1, cW2, cb2, cW3, cb3, dW2, db2, cellOut);

    // stageDE with programmatic stream serialization (overlaps BC)
    {
        cudaLaunchConfig_t cfg = {};
        cfg.gridDim  = dim3(384, 1, 1);
        cfg.blockDim = dim3(256, 1, 1);
        cfg.dynamicSmemBytes = 0;
        cfg.stream = 0;
        cudaLaunchAttribute attrs[1];
        attrs[0].id = cudaLaunchAttributeProgrammaticStreamSerialization;
        attrs[0].val.programmaticStreamSerializationAllowed = 1;
        cfg.attrs = attrs;
        cfg.numAttrs = 1;
        cudaLaunchKernelEx(&cfg, stageDE, gW1, gb1, gW2, gb2, eW1, eb1, eb2);
    }

    const size_t csmem = (size_t)GT * 128 * sizeof(float4);   // 73728 B
    cudaFuncSetAttribute(combine_kernel,
                         cudaFuncAttributeMaxDynamicSharedMemorySize, (int)csmem);
    {
        cudaLaunchConfig_t cfg = {};
        cfg.gridDim  = dim3((G_ + GT - 1) / GT, B_ / 16, 1);
        cfg.blockDim = dim3(512, 1, 1);
        cfg.dynamicSmemBytes = csmem;
        cfg.stream = 0;
        cudaLaunchAttribute attrs[1];
        attrs[0].id = cudaLaunchAttributeProgrammaticStreamSerialization;
        attrs[0].val.programmaticStreamSerializationAllowed = 1;
        cfg.attrs = attrs;
        cfg.numAttrs = 1;
        cudaLaunchKernelEx(&cfg, combine_kernel, eW2, pred);
    }
}

// round 16
// speedup vs baseline: 1.0214x; 1.0214x over previous
#include <cuda_runtime.h>
#include <cuda_bf16.h>
#include <math.h>

#define B_   256
#define A_   64
#define G_   978
#define DDRUG 128
#define DCELL 50
#define CELLIN 978
#define DOSEIN 12
#define GLOBAL_ 306   // 128+50+128
#define EXPIN 434
#define E_   4
#define H_   128

#define NCHUNK 16     // k-split for cell L1
#define GT    36      // combine gene tile (36*128*16B = 72KB dynamic smem)

// -------- device scratch --------
__device__ float d_gfeat[B_ * GLOBAL_];
__device__ float d_c1p[NCHUNK * B_ * 200];  // cell L1 partials [chunk][row][200]
__device__ __align__(16) float d_U[B_ * E_ * H_];   // [b][e*128+h]
__device__ __align__(16) float d_V[G_ * E_ * H_];   // [g][e*128+h]
__device__ int   d_eidx[B_ * 2];
__device__ float d_gw[B_ * 2];
__device__ float d_biasc[B_];

// =========================================================
// Stage A (inputs only), 256 threads, grid 828:
//   [0,128)    drug atom-sum, 2 rows/block
//   [128,640)  cell L1 partials: 16 k-chunks x 32 row-tiles (RB=8)
//   [640,704)  dose L1+L2 fused: 4 rows/block -> gfeat[:,178:306)
//   [704,828)  V = gene_emb @ eW1[:,306:,:]: 62 tiles(16) x 2 expert-pairs
// =========================================================
__global__ void __launch_bounds__(256) stageA(
    const float* __restrict__ drug,
    const float* __restrict__ gex,
    const float* __restrict__ cW1,
    const float* __restrict__ idose,
    const float* __restrict__ dW1, const float* __restrict__ db1,
    const float* __restrict__ dW2, const float* __restrict__ db2,
    const float* __restrict__ gene_emb,
    const float* __restrict__ eW1)
{
    __shared__ __align__(16) float sA[16 * 128];
    const int blk = blockIdx.x;
    const int t = threadIdx.x;

    if (blk < 128) {
        int b = blk * 2 + (t >> 7);
        int d = t & 127;
        const float* p = drug + (size_t)b * A_ * DDRUG + d;
        float s = 0.f;
#pragma unroll
        for (int a = 0; a < A_; a++) s += p[a * DDRUG];
        d_gfeat[b * GLOBAL_ + d] = s;

    } else if (blk < 640) {
        // ---- cell L1 partial: chunk c (of 16), rows r0..r0+7 ----
        int idx = blk - 128;
        int c = idx >> 5, rt = idx & 31;
        int r0 = rt * 8;
        int k0 = (CELLIN * c) / NCHUNK;
        int k1 = (CELLIN * (c + 1)) / NCHUNK;
        int kc = k1 - k0;                 // 61 or 62
        const int Kp = 64;
        for (int i = t; i < 8 * Kp; i += 256) {
            int r = i >> 6, k = i & 63;
            sA[i] = (k < kc) ? gex[(r0 + r) * CELLIN + k0 + k] : 0.f;
        }
        __syncthreads();
        if (t < 200) {
            float acc[8];
#pragma unroll
            for (int r = 0; r < 8; r++) acc[r] = 0.f;
            int k = 0;
            for (; k + 8 <= kc; k += 8) {
                float w[8];
#pragma unroll
                for (int j = 0; j < 8; j++)
                    w[j] = cW1[(k0 + k + j) * 200 + t];
#pragma unroll
                for (int r = 0; r < 8; r++) {
                    float4 xa = *reinterpret_cast<const float4*>(sA + r * Kp + k);
                    float4 xb = *reinterpret_cast<const float4*>(sA + r * Kp + k + 4);
                    acc[r] = fmaf(xa.x, w[0], acc[r]);
                    acc[r] = fmaf(xa.y, w[1], acc[r]);
                    acc[r] = fmaf(xa.z, w[2], acc[r]);
                    acc[r] = fmaf(xa.w, w[3], acc[r]);
                    acc[r] = fmaf(xb.x, w[4], acc[r]);
                    acc[r] = fmaf(xb.y, w[5], acc[r]);
                    acc[r] = fmaf(xb.z, w[6], acc[r]);
                    acc[r] = fmaf(xb.w, w[7], acc[r]);
                }
            }
            for (; k < kc; k++) {
                float w = cW1[(k0 + k) * 200 + t];
#pragma unroll
                for (int r = 0; r < 8; r++)
                    acc[r] = fmaf(sA[r * Kp + k], w, acc[r]);
            }
#pragma unroll
            for (int r = 0; r < 8; r++)
                d_c1p[(c * B_ + r0 + r) * 200 + t] = acc[r];
        }

    } else if (blk < 704) {
        // ---- dose L1+L2 fused: 4 rows ----
        int r0 = (blk - 640) * 4;
        float* sD1 = sA;                 // [4][64]
        float* sDo = sA + 256;           // (unused beyond clarity)
        (void)sDo;
        {
            int row = t >> 6, col = t & 63;   // 256 threads = 4x64
            float a = db1[col];
            const float* x = idose + (r0 + row) * DOSEIN;
#pragma unroll
            for (int k = 0; k < DOSEIN; k++)
                a = fmaf(x[k], dW1[k * 64 + col], a);
            sD1[row * 64 + col] = fmaxf(a, 0.f);
        }
        __syncthreads();
#pragma unroll
        for (int rr = 0; rr < 2; rr++) {
            int row = rr * 2 + (t >> 7);
            int col = t & 127;
            float a = db2[col];
            for (int k = 0; k < 64; k += 8) {
                float w[8];
#pragma unroll
                for (int j = 0; j < 8; j++)
                    w[j] = dW2[(k + j) * 128 + col];
                float4 xa = *reinterpret_cast<const float4*>(sD1 + row * 64 + k);
                float4 xb = *reinterpret_cast<const float4*>(sD1 + row * 64 + k + 4);
                a = fmaf(xa.x, w[0], a);
                a = fmaf(xa.y, w[1], a);
                a = fmaf(xa.z, w[2], a);
                a = fmaf(xa.w, w[3], a);
                a = fmaf(xb.x, w[4], a);
                a = fmaf(xb.y, w[5], a);
                a = fmaf(xb.z, w[6], a);
                a = fmaf(xb.w, w[7], a);
            }
            d_gfeat[(r0 + row) * GLOBAL_ + 178 + col] = fmaxf(a, 0.f);
        }

    } else {
        // ---- V: 16 genes x 2 experts per block ----
        int idx = blk - 704;             // 0..123
        int rt = idx >> 1, ep = idx & 1;
        int r0 = rt * 16;
        int e = ep * 2 + (t >> 7), h = t & 127;
        for (int i = t; i < 16 * 128; i += 256) {
            int r = i >> 7, k = i & 127;
            sA[i] = (r0 + r < G_) ? gene_emb[(r0 + r) * 128 + k] : 0.f;
        }
        __syncthreads();
        float acc[16];
#pragma unroll
        for (int r = 0; r < 16; r++) acc[r] = 0.f;
        const float* Wv = eW1 + (size_t)e * EXPIN * H_ + (size_t)GLOBAL_ * H_ + h;
#pragma unroll 1
        for (int k = 0; k < 128; k += 8) {
            float w[8];
#pragma unroll
            for (int j = 0; j < 8; j++)
                w[j] = Wv[(k + j) * H_];
#pragma unroll
            for (int r = 0; r < 16; r++) {
                float4 xa = *reinterpret_cast<const float4*>(sA + r * 128 + k);
                float4 xb = *reinterpret_cast<const float4*>(sA + r * 128 + k + 4);
                acc[r] = fmaf(xa.x, w[0], acc[r]);
                acc[r] = fmaf(xa.y, w[1], acc[r]);
                acc[r] = fmaf(xa.z, w[2], acc[r]);
                acc[r] = fmaf(xa.w, w[3], acc[r]);
                acc[r] = fmaf(xb.x, w[4], acc[r]);
                acc[r] = fmaf(xb.y, w[5], acc[r]);
                acc[r] = fmaf(xb.z, w[6], acc[r]);
                acc[r] = fmaf(xb.w, w[7], acc[r]);
            }
        }
#pragma unroll
        for (int r = 0; r < 16; r++)
            if (r0 + r < G_) d_V[(r0 + r) * (E_ * H_) + e * H_ + h] = acc[r];
    }
}

// =========================================================
// Stage BC, 256 threads, grid 128 (cell path only), 2 rows/block.
// =========================================================
__global__ void __launch_bounds__(256) stageBC(
    const float* __restrict__ cb1,
    const float* __restrict__ cW2, const float* __restrict__ cb2,
    const float* __restrict__ cW3, const float* __restrict__ cb3,
    float* __restrict__ cellOut)
{
    __shared__ __align__(16) float sA[2 * 200];
    __shared__ __align__(16) float sH[2 * 100];
    const int t = threadIdx.x;
    int r0 = blockIdx.x * 2;

    for (int i = t; i < 2 * 200; i += 256) {
        int r = i / 200, k = i - r * 200;
        float s = cb1[k];
#pragma unroll
        for (int c = 0; c < NCHUNK; c++)
            s += d_c1p[(c * B_ + r0 + r) * 200 + k];
        sA[i] = fmaxf(s, 0.f);
    }
    __syncthreads();
    if (t < 100) {
        float acc[2];
#pragma unroll
        for (int r = 0; r < 2; r++) acc[r] = cb2[t];
        for (int k = 0; k < 200; k += 8) {
            float w[8];
#pragma unroll
            for (int j = 0; j < 8; j++)
                w[j] = cW2[(k + j) * 100 + t];
#pragma unroll
            for (int r = 0; r < 2; r++) {
                float4 xa = *reinterpret_cast<const float4*>(sA + r * 200 + k);
                float4 xb = *reinterpret_cast<const float4*>(sA + r * 200 + k + 4);
                acc[r] = fmaf(xa.x, w[0], acc[r]);
                acc[r] = fmaf(xa.y, w[1], acc[r]);
                acc[r] = fmaf(xa.z, w[2], acc[r]);
                acc[r] = fmaf(xa.w, w[3], acc[r]);
                acc[r] = fmaf(xb.x, w[4], acc[r]);
                acc[r] = fmaf(xb.y, w[5], acc[r]);
                acc[r] = fmaf(xb.z, w[6], acc[r]);
                acc[r] = fmaf(xb.w, w[7], acc[r]);
            }
        }
#pragma unroll
        for (int r = 0; r < 2; r++)
            sH[r * 100 + t] = fmaxf(acc[r], 0.f);
    }
    __syncthreads();
    if (t < 50) {
        float acc[2];
#pragma unroll
        for (int r = 0; r < 2; r++) acc[r] = cb3[t];
        for (int k = 0; k < 100; k += 4) {
            float w0 = cW3[(k + 0) * 50 + t];
            float w1 = cW3[(k + 1) * 50 + t];
            float w2 = cW3[(k + 2) * 50 + t];
            float w3 = cW3[(k + 3) * 50 + t];
#pragma unroll
            for (int r = 0; r < 2; r++) {
                float4 x = *reinterpret_cast<const float4*>(sH + r * 100 + k);
                acc[r] = fmaf(x.x, w0, acc[r]);
                acc[r] = fmaf(x.y, w1, acc[r]);
                acc[r] = fmaf(x.z, w2, acc[r]);
                acc[r] = fmaf(x.w, w3, acc[r]);
            }
        }
#pragma unroll
        for (int r = 0; r < 2; r++) {
            float v = fmaxf(acc[r], 0.f);
            d_gfeat[(r0 + r) * GLOBAL_ + 128 + t] = v;
            if (cellOut) cellOut[(r0 + r) * DCELL + t] = v;
        }
    }
}

// =========================================================
// Stage DE, 256 threads, grid 384 (normal launch, as in R14):
//   [0,128)   gating: 2 rows/block, hidden GEMM k-split in half
//   [128,384) U: 2 rows x 2 experts per block
// Triggers programmatic launch completion at start so the combine
// kernel's V-prefetch can overlap DE execution.
// =========================================================
__global__ void __launch_bounds__(256) stageDE(
    const float* __restrict__ gW1, const float* __restrict__ gb1,
    const float* __restrict__ gW2, const float* __restrict__ gb2,
    const float* __restrict__ eW1, const float* __restrict__ eb1,
    const float* __restrict__ eb2)
{
#if __CUDA_ARCH__ >= 900
    cudaTriggerProgrammaticLaunchCompletion();
#endif
    __shared__ __align__(16) float sG[2 * 308];
    const int blk = blockIdx.x;
    const int t = threadIdx.x;

    if (blk < 128) {
        __shared__ float sHp[2][2][128];
        __shared__ float sH[2 * 128];
        __shared__ float sL[8];
        int b0 = blk * 2;
        for (int i = t; i < 2 * 308; i += 256) {
            int r = i / 308, k = i - r * 308;
            sG[i] = (k < GLOBAL_) ? d_gfeat[(b0 + r) * GLOBAL_ + k] : 0.f;
        }
        __syncthreads();
        {
            int half = t >> 7, h = t & 127;
            float acc[2] = {0.f, 0.f};
            int kA = half ? 152 : 0;
            int kE = half ? 304 : 152;
            for (int k = kA; k < kE; k += 8) {
                float w[8];
#pragma unroll
                for (int j = 0; j < 8; j++)
                    w[j] = gW1[(k + j) * 128 + h];
#pragma unroll
                for (int r = 0; r < 2; r++) {
                    float4 xa = *reinterpret_cast<const float4*>(sG + r * 308 + k);
                    float4 xb = *reinterpret_cast<const float4*>(sG + r * 308 + k + 4);
                    acc[r] = fmaf(xa.x, w[0], acc[r]);
                    acc[r] = fmaf(xa.y, w[1], acc[r]);
                    acc[r] = fmaf(xa.z, w[2], acc[r]);
                    acc[r] = fmaf(xa.w, w[3], acc[r]);
                    acc[r] = fmaf(xb.x, w[4], acc[r]);
                    acc[r] = fmaf(xb.y, w[5], acc[r]);
                    acc[r] = fmaf(xb.z, w[6], acc[r]);
                    acc[r] = fmaf(xb.w, w[7], acc[r]);
                }
            }
            if (half) {
                for (int k = 304; k < GLOBAL_; k++) {
                    float w = gW1[k * 128 + h];
#pragma unroll
                    for (int r = 0; r < 2; r++)
                        acc[r] = fmaf(sG[r * 308 + k], w, acc[r]);
                }
            }
#pragma unroll
            for (int r = 0; r < 2; r++) sHp[half][r][h] = acc[r];
        }
        __syncthreads();
        if (t < 128) {
            float bb = gb1[t];
#pragma unroll
            for (int r = 0; r < 2; r++)
                sH[r * 128 + t] = fmaxf(sHp[0][r][t] + sHp[1][r][t] + bb, 0.f);
        }
        __syncthreads();
        if (t < 8) {
            int r = t >> 2, e = t & 3;
            float a = gb2[e];
            for (int k = 0; k < 128; k++)
                a = fmaf(sH[r * 128 + k], gW2[k * 4 + e], a);
            sL[t] = a;
        }
        __syncthreads();
        if (t < 2) {
            int b = b0 + t;
            float v[4];
#pragma unroll
            for (int j = 0; j < 4; j++) v[j] = sL[t * 4 + j];
            int i0 = 0;
#pragma unroll
            for (int j = 1; j < 4; j++) if (v[j] > v[i0]) i0 = j;
            int i1 = (i0 == 0) ? 1 : 0;
#pragma unroll
            for (int j = 0; j < 4; j++) if (j != i0 && v[j] > v[i1]) i1 = j;
            float m  = fmaxf(v[i0], v[i1]);
            float e0 = __expf(v[i0] - m), e1 = __expf(v[i1] - m);
            float inv = 1.f / (e0 + e1);
            float w0 = e0 * inv, w1 = e1 * inv;
            d_eidx[2 * b]     = i0;
            d_eidx[2 * b + 1] = i1;
            d_gw[2 * b]       = w0;
            d_gw[2 * b + 1]   = w1;
            d_biasc[b]        = w0 * eb2[i0] + w1 * eb2[i1];
        }
    } else {
        // U: 2 rows x 2 experts per block
        int idx = blk - 128;             // 0..255
        int rt = idx >> 1, ep = idx & 1;
        int r0 = rt * 2;
        int e = ep * 2 + (t >> 7), h = t & 127;
        for (int i = t; i < 2 * 308; i += 256) {
            int r = i / 308, k = i - r * 308;
            sG[i] = (k < GLOBAL_) ? d_gfeat[(r0 + r) * GLOBAL_ + k] : 0.f;
        }
        __syncthreads();
        float acc[2];
        float bb = eb1[e * H_ + h];
#pragma unroll
        for (int r = 0; r < 2; r++) acc[r] = bb;
        const float* Wp = eW1 + (size_t)e * EXPIN * H_ + h;
#pragma unroll 1
        for (int k = 0; k < 304; k += 8) {
            float w[8];
#pragma unroll
            for (int j = 0; j < 8; j++)
                w[j] = Wp[(k + j) * H_];
#pragma unroll
            for (int r = 0; r < 2; r++) {
                float4 xa = *reinterpret_cast<const float4*>(sG + r * 308 + k);
                float4 xb = *reinterpret_cast<const float4*>(sG + r * 308 + k + 4);
                acc[r] = fmaf(xa.x, w[0], acc[r]);
                acc[r] = fmaf(xa.y, w[1], acc[r]);
                acc[r] = fmaf(xa.z, w[2], acc[r]);
                acc[r] = fmaf(xa.w, w[3], acc[r]);
                acc[r] = fmaf(xb.x, w[4], acc[r]);
                acc[r] = fmaf(xb.y, w[5], acc[r]);
                acc[r] = fmaf(xb.z, w[6], acc[r]);
                acc[r] = fmaf(xb.w, w[7], acc[r]);
            }
        }
        for (int k = 304; k < GLOBAL_; k++) {
            float w = Wp[k * H_];
#pragma unroll
            for (int r = 0; r < 2; r++)
                acc[r] = fmaf(sG[r * 308 + k], w, acc[r]);
        }
#pragma unroll
        for (int r = 0; r < 2; r++)
            d_U[(r0 + r) * (E_ * H_) + e * H_ + h] = acc[r];
    }
}

// =========================================================
// Combine: warp = one b, 36-gene tile (dynamic smem, single wave),
// paired-gene merged reduce, fully unrolled full-tile path, PDL
// (pre-sync V prefetch; d_V produced by stageA, strictly before DE).
// =========================================================
struct CombCtx {
    const float4* sVbase0;   // sV + e0*32 + lane
    const float4* sVbase1;   // sV + e1*32 + lane
    float4 u0, u1, w20, w21;
    float bc;
    float* outp;             // pred + b*G_ + g0
    int lane;
};

__device__ __forceinline__ void comb_pair(const CombCtx& c, int gi)
{
    float4 va0 = c.sVbase0[(gi + 0) * 128];
    float4 va1 = c.sVbase1[(gi + 0) * 128];
    float4 vb0 = c.sVbase0[(gi + 1) * 128];
    float4 vb1 = c.sVbase1[(gi + 1) * 128];

    float p0 =           fmaxf(c.u0.x + va0.x, 0.f) * c.w20.x;
    p0 = fmaf(fmaxf(c.u0.y + va0.y, 0.f), c.w20.y, p0);
    p0 = fmaf(fmaxf(c.u0.z + va0.z, 0.f), c.w20.z, p0);
    p0 = fmaf(fmaxf(c.u0.w + va0.w, 0.f), c.w20.w, p0);
    p0 = fmaf(fmaxf(c.u1.x + va1.x, 0.f), c.w21.x, p0);
    p0 = fmaf(fmaxf(c.u1.y + va1.y, 0.f), c.w21.y, p0);
    p0 = fmaf(fmaxf(c.u1.z + va1.z, 0.f), c.w21.z, p0);
    p0 = fmaf(fmaxf(c.u1.w + va1.w, 0.f), c.w21.w, p0);

    float p1 =           fmaxf(c.u0.x + vb0.x, 0.f) * c.w20.x;
    p1 = fmaf(fmaxf(c.u0.y + vb0.y, 0.f), c.w20.y, p1);
    p1 = fmaf(fmaxf(c.u0.z + vb0.z, 0.f), c.w20.z, p1);
    p1 = fmaf(fmaxf(c.u0.w + vb0.w, 0.f), c.w20.w, p1);
    p1 = fmaf(fmaxf(c.u1.x + vb1.x, 0.f), c.w21.x, p1);
    p1 = fmaf(fmaxf(c.u1.y + vb1.y, 0.f), c.w21.y, p1);
    p1 = fmaf(fmaxf(c.u1.z + vb1.z, 0.f), c.w21.z, p1);
    p1 = fmaf(fmaxf(c.u1.w + vb1.w, 0.f), c.w21.w, p1);

    float z0 = p0 + __shfl_xor_sync(0xffffffffu, p0, 16);
    float z1 = p1 + __shfl_xor_sync(0xffffffffu, p1, 16);
    float s  = (c.lane & 16) ? z1 : z0;
    s += __shfl_xor_sync(0xffffffffu, s, 8);
    s += __shfl_xor_sync(0xffffffffu, s, 4);
    s += __shfl_xor_sync(0xffffffffu, s, 2);
    s += __shfl_xor_sync(0xffffffffu, s, 1);
    if (c.lane == 0)
        c.outp[gi] = s + c.bc;
    else if (c.lane == 16)
        c.outp[gi + 1] = s + c.bc;
}

__global__ void __launch_bounds__(512) combine_kernel(
    const float* __restrict__ expW2, float* __restrict__ pred)
{
    extern __shared__ float4 sV[];       // GT*128 float4 = 72KB
    const int g0   = blockIdx.x * GT;
    const int warp = threadIdx.x >> 5;
    const int lane = threadIdx.x & 31;
    const int b    = blockIdx.y * 16 + warp;
    const int nG   = (G_ - g0) < GT ? (G_ - g0) : GT;   // 36 or 6 (even)

    const float4* V4 = reinterpret_cast<const float4*>(d_V);
    for (int i = threadIdx.x; i < nG * 128; i += blockDim.x)
        sV[i] = V4[g0 * 128 + i];
    __syncthreads();

#if __CUDA_ARCH__ >= 900
    cudaGridDependencySynchronize();     // wait for stageDE outputs
#endif

    const int   e0  = d_eidx[2 * b], e1 = d_eidx[2 * b + 1];
    const float gw0 = d_gw[2 * b],   gw1 = d_gw[2 * b + 1];

    const float4* U4 = reinterpret_cast<const float4*>(d_U) + b * 128;
    const float4* W4 = reinterpret_cast<const float4*>(expW2);

    CombCtx c;
    c.lane = lane;
    c.bc   = d_biasc[b];
    c.outp = pred + b * G_ + g0;
    c.sVbase0 = sV + e0 * 32 + lane;
    c.sVbase1 = sV + e1 * 32 + lane;
    c.u0 = U4[e0 * 32 + lane];
    c.u1 = U4[e1 * 32 + lane];
    float4 w20 = W4[e0 * 32 + lane];
    w20.x *= gw0; w20.y *= gw0; w20.z *= gw0; w20.w *= gw0;
    float4 w21 = W4[e1 * 32 + lane];
    w21.x *= gw1; w21.y *= gw1; w21.z *= gw1; w21.w *= gw1;
    c.w20 = w20; c.w21 = w21;

    if (nG == GT) {
#pragma unroll
        for (int gi = 0; gi < GT; gi += 2)
            comb_pair(c, gi);
    } else {
#pragma unroll
        for (int gi = 0; gi < 6; gi += 2)     // tail tile: nG = 6
            comb_pair(c, gi);
    }
}

// =========================================================
extern "C" void kernel_launch(void* const* d_in, const int* in_sizes, int n_in,
                              void* d_out, int out_size)
{
    const float* drug_atom = (const float*)d_in[0];
    const float* gex       = (const float*)d_in[1];
    const float* idose     = (const float*)d_in[2];
    const float* cW1 = (const float*)d_in[3];  const float* cb1 = (const float*)d_in[4];
    const float* cW2 = (const float*)d_in[5];  const float* cb2 = (const float*)d_in[6];
    const float* cW3 = (const float*)d_in[7];  const float* cb3 = (const float*)d_in[8];
    const float* dW1 = (const float*)d_in[9];  const float* db1 = (const float*)d_in[10];
    const float* dW2 = (const float*)d_in[11]; const float* db2 = (const float*)d_in[12];
    const float* gene_emb = (const float*)d_in[13];
    const float* gW1 = (const float*)d_in[14]; const float* gb1 = (const float*)d_in[15];
    const float* gW2 = (const float*)d_in[16]; const float* gb2 = (const float*)d_in[17];
    const float* eW1 = (const float*)d_in[18]; const float* eb1 = (const float*)d_in[19];
    const float* eW2 = (const float*)d_in[20]; const float* eb2 = (const float*)d_in[21];

    float* pred = (float*)d_out;
    float* cellOut = (out_size >= B_ * G_ + B_ * DCELL) ? pred + B_ * G_ : nullptr;

    stageA<<<828, 256>>>(drug_atom, gex, cW1, idose, dW1, db1, dW2, db2,
                         gene_emb, eW1);
    stageBC<<<128, 256>>>(cb1, cW2, cb2, cW3, cb3, cellOut);
    stageDE<<<384, 256>>>(gW1, gb1, gW2, gb2, eW1, eb1, eb2);

    const size_t csmem = (size_t)GT * 128 * sizeof(float4);   // 73728 B
    cudaFuncSetAttribute(combine_kernel,
                         cudaFuncAttributeMaxDynamicSharedMemorySize, (int)csmem);
    {
        cudaLaunchConfig_t cfg = {};
        cfg.gridDim  = dim3((G_ + GT - 1) / GT, B_ / 16, 1);
        cfg.blockDim = dim3(512, 1, 1);
        cfg.dynamicSmemBytes = csmem;
        cfg.stream = 0;
        cudaLaunchAttribute attrs[1];
        attrs[0].id = cudaLaunchAttributeProgrammaticStreamSerialization;
        attrs[0].val.programmaticStreamSerializationAllowed = 1;
        cfg.attrs = attrs;
        cfg.numAttrs = 1;
        cudaLaunchKernelEx(&cfg, combine_kernel, eW2, pred);
    }
}

// round 17
// speedup vs baseline: 1.0765x; 1.0539x over previous
#include <cuda_runtime.h>
#include <cuda_bf16.h>
#include <math.h>

#define B_   256
#define A_   64
#define G_   978
#define DDRUG 128
#define DCELL 50
#define CELLIN 978
#define DOSEIN 12
#define GLOBAL_ 306   // 128+50+128
#define EXPIN 434
#define E_   4
#define H_   128

#define NCHUNK 16     // k-split for cell L1
#define GT    36      // combine gene tile (36*128*16B = 72KB dynamic smem)

// -------- device scratch --------
__device__ float d_gfeat[B_ * GLOBAL_];
__device__ float d_c1p[NCHUNK * B_ * 200];  // cell L1 partials [chunk][row][200]
__device__ __align__(16) float d_U[B_ * E_ * H_];   // [b][e*128+h]
__device__ __align__(16) float d_V[G_ * E_ * H_];   // [g][e*128+h]
__device__ int   d_eidx[B_ * 2];
__device__ float d_gw[B_ * 2];
__device__ float d_biasc[B_];

// =========================================================
// Stage A (inputs only), 256 threads, grid 704:
//   [0,128)    drug atom-sum, 2 rows/block
//   [128,640)  cell L1 partials: 16 k-chunks x 32 row-tiles (RB=8)
//   [640,704)  dose L1+L2 fused: 4 rows/block -> gfeat[:,178:306)
// =========================================================
__global__ void __launch_bounds__(256) stageA(
    const float* __restrict__ drug,
    const float* __restrict__ gex,
    const float* __restrict__ cW1,
    const float* __restrict__ idose,
    const float* __restrict__ dW1, const float* __restrict__ db1,
    const float* __restrict__ dW2, const float* __restrict__ db2)
{
    __shared__ __align__(16) float sA[8 * 64];
    const int blk = blockIdx.x;
    const int t = threadIdx.x;

    if (blk < 128) {
        int b = blk * 2 + (t >> 7);
        int d = t & 127;
        const float* p = drug + (size_t)b * A_ * DDRUG + d;
        float s = 0.f;
#pragma unroll
        for (int a = 0; a < A_; a++) s += p[a * DDRUG];
        d_gfeat[b * GLOBAL_ + d] = s;

    } else if (blk < 640) {
        // ---- cell L1 partial: chunk c (of 16), rows r0..r0+7 ----
        int idx = blk - 128;
        int c = idx >> 5, rt = idx & 31;
        int r0 = rt * 8;
        int k0 = (CELLIN * c) / NCHUNK;
        int k1 = (CELLIN * (c + 1)) / NCHUNK;
        int kc = k1 - k0;                 // 61 or 62
        const int Kp = 64;
        for (int i = t; i < 8 * Kp; i += 256) {
            int r = i >> 6, k = i & 63;
            sA[i] = (k < kc) ? gex[(r0 + r) * CELLIN + k0 + k] : 0.f;
        }
        __syncthreads();
        if (t < 200) {
            float acc[8];
#pragma unroll
            for (int r = 0; r < 8; r++) acc[r] = 0.f;
            int k = 0;
            for (; k + 8 <= kc; k += 8) {
                float w[8];
#pragma unroll
                for (int j = 0; j < 8; j++)
                    w[j] = cW1[(k0 + k + j) * 200 + t];
#pragma unroll
                for (int r = 0; r < 8; r++) {
                    float4 xa = *reinterpret_cast<const float4*>(sA + r * Kp + k);
                    float4 xb = *reinterpret_cast<const float4*>(sA + r * Kp + k + 4);
                    acc[r] = fmaf(xa.x, w[0], acc[r]);
                    acc[r] = fmaf(xa.y, w[1], acc[r]);
                    acc[r] = fmaf(xa.z, w[2], acc[r]);
                    acc[r] = fmaf(xa.w, w[3], acc[r]);
                    acc[r] = fmaf(xb.x, w[4], acc[r]);
                    acc[r] = fmaf(xb.y, w[5], acc[r]);
                    acc[r] = fmaf(xb.z, w[6], acc[r]);
                    acc[r] = fmaf(xb.w, w[7], acc[r]);
                }
            }
            for (; k < kc; k++) {
                float w = cW1[(k0 + k) * 200 + t];
#pragma unroll
                for (int r = 0; r < 8; r++)
                    acc[r] = fmaf(sA[r * Kp + k], w, acc[r]);
            }
#pragma unroll
            for (int r = 0; r < 8; r++)
                d_c1p[(c * B_ + r0 + r) * 200 + t] = acc[r];
        }

    } else {
        // ---- dose L1+L2 fused: 4 rows ----
        int r0 = (blk - 640) * 4;
        float* sD1 = sA;                 // [4][64]
        {
            int row = t >> 6, col = t & 63;   // 256 threads = 4x64
            float a = db1[col];
            const float* x = idose + (r0 + row) * DOSEIN;
#pragma unroll
            for (int k = 0; k < DOSEIN; k++)
                a = fmaf(x[k], dW1[k * 64 + col], a);
            sD1[row * 64 + col] = fmaxf(a, 0.f);
        }
        __syncthreads();
#pragma unroll
        for (int rr = 0; rr < 2; rr++) {
            int row = rr * 2 + (t >> 7);
            int col = t & 127;
            float a = db2[col];
            for (int k = 0; k < 64; k += 8) {
                float w[8];
#pragma unroll
                for (int j = 0; j < 8; j++)
                    w[j] = dW2[(k + j) * 128 + col];
                float4 xa = *reinterpret_cast<const float4*>(sD1 + row * 64 + k);
                float4 xb = *reinterpret_cast<const float4*>(sD1 + row * 64 + k + 4);
                a = fmaf(xa.x, w[0], a);
                a = fmaf(xa.y, w[1], a);
                a = fmaf(xa.z, w[2], a);
                a = fmaf(xa.w, w[3], a);
                a = fmaf(xb.x, w[4], a);
                a = fmaf(xb.y, w[5], a);
                a = fmaf(xb.z, w[6], a);
                a = fmaf(xb.w, w[7], a);
            }
            d_gfeat[(r0 + row) * GLOBAL_ + 178 + col] = fmaxf(a, 0.f);
        }
    }
}

// =========================================================
// Stage BC, 256 threads, grid 252:
//   [0,128)   cell L2+L3 fused, 2 rows/block
//   [128,252) V = gene_emb @ eW1[:,306:,:]: 62 tiles(16) x 2 expert-pairs
//             (input-only; placed here to fill SMs idle during cell path)
// =========================================================
__global__ void __launch_bounds__(256) stageBC(
    const float* __restrict__ cb1,
    const float* __restrict__ cW2, const float* __restrict__ cb2,
    const float* __restrict__ cW3, const float* __restrict__ cb3,
    const float* __restrict__ gene_emb,
    const float* __restrict__ eW1,
    float* __restrict__ cellOut)
{
    __shared__ __align__(16) float sBuf[16 * 128];   // 8KB shared by both paths
    const int blk = blockIdx.x;
    const int t = threadIdx.x;

    if (blk < 128) {
        float* sA = sBuf;            // [2][200]
        float* sH = sBuf + 400;      // [2][100]
        int r0 = blk * 2;

        for (int i = t; i < 2 * 200; i += 256) {
            int r = i / 200, k = i - r * 200;
            float s = cb1[k];
#pragma unroll
            for (int c = 0; c < NCHUNK; c++)
                s += d_c1p[(c * B_ + r0 + r) * 200 + k];
            sA[i] = fmaxf(s, 0.f);
        }
        __syncthreads();
        if (t < 100) {
            float acc[2];
#pragma unroll
            for (int r = 0; r < 2; r++) acc[r] = cb2[t];
            for (int k = 0; k < 200; k += 8) {
                float w[8];
#pragma unroll
                for (int j = 0; j < 8; j++)
                    w[j] = cW2[(k + j) * 100 + t];
#pragma unroll
                for (int r = 0; r < 2; r++) {
                    float4 xa = *reinterpret_cast<const float4*>(sA + r * 200 + k);
                    float4 xb = *reinterpret_cast<const float4*>(sA + r * 200 + k + 4);
                    acc[r] = fmaf(xa.x, w[0], acc[r]);
                    acc[r] = fmaf(xa.y, w[1], acc[r]);
                    acc[r] = fmaf(xa.z, w[2], acc[r]);
                    acc[r] = fmaf(xa.w, w[3], acc[r]);
                    acc[r] = fmaf(xb.x, w[4], acc[r]);
                    acc[r] = fmaf(xb.y, w[5], acc[r]);
                    acc[r] = fmaf(xb.z, w[6], acc[r]);
                    acc[r] = fmaf(xb.w, w[7], acc[r]);
                }
            }
#pragma unroll
            for (int r = 0; r < 2; r++)
                sH[r * 100 + t] = fmaxf(acc[r], 0.f);
        }
        __syncthreads();
        if (t < 50) {
            float acc[2];
#pragma unroll
            for (int r = 0; r < 2; r++) acc[r] = cb3[t];
            for (int k = 0; k < 100; k += 4) {
                float w0 = cW3[(k + 0) * 50 + t];
                float w1 = cW3[(k + 1) * 50 + t];
                float w2 = cW3[(k + 2) * 50 + t];
                float w3 = cW3[(k + 3) * 50 + t];
#pragma unroll
                for (int r = 0; r < 2; r++) {
                    float4 x = *reinterpret_cast<const float4*>(sH + r * 100 + k);
                    acc[r] = fmaf(x.x, w0, acc[r]);
                    acc[r] = fmaf(x.y, w1, acc[r]);
                    acc[r] = fmaf(x.z, w2, acc[r]);
                    acc[r] = fmaf(x.w, w3, acc[r]);
                }
            }
#pragma unroll
            for (int r = 0; r < 2; r++) {
                float v = fmaxf(acc[r], 0.f);
                d_gfeat[(r0 + r) * GLOBAL_ + 128 + t] = v;
                if (cellOut) cellOut[(r0 + r) * DCELL + t] = v;
            }
        }
    } else {
        // ---- V: 16 genes x 2 experts per block ----
        float* sA = sBuf;
        int idx = blk - 128;             // 0..123
        int rt = idx >> 1, ep = idx & 1;
        int r0 = rt * 16;
        int e = ep * 2 + (t >> 7), h = t & 127;
        for (int i = t; i < 16 * 128; i += 256) {
            int r = i >> 7, k = i & 127;
            sA[i] = (r0 + r < G_) ? gene_emb[(r0 + r) * 128 + k] : 0.f;
        }
        __syncthreads();
        float acc[16];
#pragma unroll
        for (int r = 0; r < 16; r++) acc[r] = 0.f;
        const float* Wv = eW1 + (size_t)e * EXPIN * H_ + (size_t)GLOBAL_ * H_ + h;
#pragma unroll 1
        for (int k = 0; k < 128; k += 8) {
            float w[8];
#pragma unroll
            for (int j = 0; j < 8; j++)
                w[j] = Wv[(k + j) * H_];
#pragma unroll
            for (int r = 0; r < 16; r++) {
                float4 xa = *reinterpret_cast<const float4*>(sA + r * 128 + k);
                float4 xb = *reinterpret_cast<const float4*>(sA + r * 128 + k + 4);
                acc[r] = fmaf(xa.x, w[0], acc[r]);
                acc[r] = fmaf(xa.y, w[1], acc[r]);
                acc[r] = fmaf(xa.z, w[2], acc[r]);
                acc[r] = fmaf(xa.w, w[3], acc[r]);
                acc[r] = fmaf(xb.x, w[4], acc[r]);
                acc[r] = fmaf(xb.y, w[5], acc[r]);
                acc[r] = fmaf(xb.z, w[6], acc[r]);
                acc[r] = fmaf(xb.w, w[7], acc[r]);
            }
        }
#pragma unroll
        for (int r = 0; r < 16; r++)
            if (r0 + r < G_) d_V[(r0 + r) * (E_ * H_) + e * H_ + h] = acc[r];
    }
}

// =========================================================
// Stage DE, 256 threads, grid 384:
//   [0,128)   gating: 2 rows/block, hidden GEMM k-split in half
//   [128,384) U: 2 rows x 2 experts per block
// Triggers programmatic launch completion at start so the combine
// kernel's V-prefetch can overlap DE execution.
// =========================================================
__global__ void __launch_bounds__(256) stageDE(
    const float* __restrict__ gW1, const float* __restrict__ gb1,
    const float* __restrict__ gW2, const float* __restrict__ gb2,
    const float* __restrict__ eW1, const float* __restrict__ eb1,
    const float* __restrict__ eb2)
{
#if __CUDA_ARCH__ >= 900
    cudaTriggerProgrammaticLaunchCompletion();
#endif
    __shared__ __align__(16) float sG[2 * 308];
    const int blk = blockIdx.x;
    const int t = threadIdx.x;

    if (blk < 128) {
        __shared__ float sHp[2][2][128];
        __shared__ float sH[2 * 128];
        __shared__ float sL[8];
        int b0 = blk * 2;
        for (int i = t; i < 2 * 308; i += 256) {
            int r = i / 308, k = i - r * 308;
            sG[i] = (k < GLOBAL_) ? d_gfeat[(b0 + r) * GLOBAL_ + k] : 0.f;
        }
        __syncthreads();
        {
            int half = t >> 7, h = t & 127;
            float acc[2] = {0.f, 0.f};
            int kA = half ? 152 : 0;
            int kE = half ? 304 : 152;
            for (int k = kA; k < kE; k += 8) {
                float w[8];
#pragma unroll
                for (int j = 0; j < 8; j++)
                    w[j] = gW1[(k + j) * 128 + h];
#pragma unroll
                for (int r = 0; r < 2; r++) {
                    float4 xa = *reinterpret_cast<const float4*>(sG + r * 308 + k);
                    float4 xb = *reinterpret_cast<const float4*>(sG + r * 308 + k + 4);
                    acc[r] = fmaf(xa.x, w[0], acc[r]);
                    acc[r] = fmaf(xa.y, w[1], acc[r]);
                    acc[r] = fmaf(xa.z, w[2], acc[r]);
                    acc[r] = fmaf(xa.w, w[3], acc[r]);
                    acc[r] = fmaf(xb.x, w[4], acc[r]);
                    acc[r] = fmaf(xb.y, w[5], acc[r]);
                    acc[r] = fmaf(xb.z, w[6], acc[r]);
                    acc[r] = fmaf(xb.w, w[7], acc[r]);
                }
            }
            if (half) {
                for (int k = 304; k < GLOBAL_; k++) {
                    float w = gW1[k * 128 + h];
#pragma unroll
                    for (int r = 0; r < 2; r++)
                        acc[r] = fmaf(sG[r * 308 + k], w, acc[r]);
                }
            }
#pragma unroll
            for (int r = 0; r < 2; r++) sHp[half][r][h] = acc[r];
        }
        __syncthreads();
        if (t < 128) {
            float bb = gb1[t];
#pragma unroll
            for (int r = 0; r < 2; r++)
                sH[r * 128 + t] = fmaxf(sHp[0][r][t] + sHp[1][r][t] + bb, 0.f);
        }
        __syncthreads();
        if (t < 8) {
            int r = t >> 2, e = t & 3;
            float a = gb2[e];
            for (int k = 0; k < 128; k++)
                a = fmaf(sH[r * 128 + k], gW2[k * 4 + e], a);
            sL[t] = a;
        }
        __syncthreads();
        if (t < 2) {
            int b = b0 + t;
            float v[4];
#pragma unroll
            for (int j = 0; j < 4; j++) v[j] = sL[t * 4 + j];
            int i0 = 0;
#pragma unroll
            for (int j = 1; j < 4; j++) if (v[j] > v[i0]) i0 = j;
            int i1 = (i0 == 0) ? 1 : 0;
#pragma unroll
            for (int j = 0; j < 4; j++) if (j != i0 && v[j] > v[i1]) i1 = j;
            float m  = fmaxf(v[i0], v[i1]);
            float e0 = __expf(v[i0] - m), e1 = __expf(v[i1] - m);
            float inv = 1.f / (e0 + e1);
            float w0 = e0 * inv, w1 = e1 * inv;
            d_eidx[2 * b]     = i0;
            d_eidx[2 * b + 1] = i1;
            d_gw[2 * b]       = w0;
            d_gw[2 * b + 1]   = w1;
            d_biasc[b]        = w0 * eb2[i0] + w1 * eb2[i1];
        }
    } else {
        // U: 2 rows x 2 experts per block
        int idx = blk - 128;             // 0..255
        int rt = idx >> 1, ep = idx & 1;
        int r0 = rt * 2;
        int e = ep * 2 + (t >> 7), h = t & 127;
        for (int i = t; i < 2 * 308; i += 256) {
            int r = i / 308, k = i - r * 308;
            sG[i] = (k < GLOBAL_) ? d_gfeat[(r0 + r) * GLOBAL_ + k] : 0.f;
        }
        __syncthreads();
        float acc[2];
        float bb = eb1[e * H_ + h];
#pragma unroll
        for (int r = 0; r < 2; r++) acc[r] = bb;
        const float* Wp = eW1 + (size_t)e * EXPIN * H_ + h;
#pragma unroll 1
        for (int k = 0; k < 304; k += 8) {
            float w[8];
#pragma unroll
            for (int j = 0; j < 8; j++)
                w[j] = Wp[(k + j) * H_];
#pragma unroll
            for (int r = 0; r < 2; r++) {
                float4 xa = *reinterpret_cast<const float4*>(sG + r * 308 + k);
                float4 xb = *reinterpret_cast<const float4*>(sG + r * 308 + k + 4);
                acc[r] = fmaf(xa.x, w[0], acc[r]);
                acc[r] = fmaf(xa.y, w[1], acc[r]);
                acc[r] = fmaf(xa.z, w[2], acc[r]);
                acc[r] = fmaf(xa.w, w[3], acc[r]);
                acc[r] = fmaf(xb.x, w[4], acc[r]);
                acc[r] = fmaf(xb.y, w[5], acc[r]);
                acc[r] = fmaf(xb.z, w[6], acc[r]);
                acc[r] = fmaf(xb.w, w[7], acc[r]);
            }
        }
        for (int k = 304; k < GLOBAL_; k++) {
            float w = Wp[k * H_];
#pragma unroll
            for (int r = 0; r < 2; r++)
                acc[r] = fmaf(sG[r * 308 + k], w, acc[r]);
        }
#pragma unroll
        for (int r = 0; r < 2; r++)
            d_U[(r0 + r) * (E_ * H_) + e * H_ + h] = acc[r];
    }
}

// =========================================================
// Combine: warp = one b, 36-gene tile (dynamic smem, single wave),
// paired-gene merged reduce, fully unrolled full-tile path, PDL
// (pre-sync V prefetch; d_V produced by stageBC, strictly before DE).
// =========================================================
struct CombCtx {
    const float4* sVbase0;   // sV + e0*32 + lane
    const float4* sVbase1;   // sV + e1*32 + lane
    float4 u0, u1, w20, w21;
    float bc;
    float* outp;             // pred + b*G_ + g0
    int lane;
};

__device__ __forceinline__ void comb_pair(const CombCtx& c, int gi)
{
    float4 va0 = c.sVbase0[(gi + 0) * 128];
    float4 va1 = c.sVbase1[(gi + 0) * 128];
    float4 vb0 = c.sVbase0[(gi + 1) * 128];
    float4 vb1 = c.sVbase1[(gi + 1) * 128];

    float p0 =           fmaxf(c.u0.x + va0.x, 0.f) * c.w20.x;
    p0 = fmaf(fmaxf(c.u0.y + va0.y, 0.f), c.w20.y, p0);
    p0 = fmaf(fmaxf(c.u0.z + va0.z, 0.f), c.w20.z, p0);
    p0 = fmaf(fmaxf(c.u0.w + va0.w, 0.f), c.w20.w, p0);
    p0 = fmaf(fmaxf(c.u1.x + va1.x, 0.f), c.w21.x, p0);
    p0 = fmaf(fmaxf(c.u1.y + va1.y, 0.f), c.w21.y, p0);
    p0 = fmaf(fmaxf(c.u1.z + va1.z, 0.f), c.w21.z, p0);
    p0 = fmaf(fmaxf(c.u1.w + va1.w, 0.f), c.w21.w, p0);

    float p1 =           fmaxf(c.u0.x + vb0.x, 0.f) * c.w20.x;
    p1 = fmaf(fmaxf(c.u0.y + vb0.y, 0.f), c.w20.y, p1);
    p1 = fmaf(fmaxf(c.u0.z + vb0.z, 0.f), c.w20.z, p1);
    p1 = fmaf(fmaxf(c.u0.w + vb0.w, 0.f), c.w20.w, p1);
    p1 = fmaf(fmaxf(c.u1.x + vb1.x, 0.f), c.w21.x, p1);
    p1 = fmaf(fmaxf(c.u1.y + vb1.y, 0.f), c.w21.y, p1);
    p1 = fmaf(fmaxf(c.u1.z + vb1.z, 0.f), c.w21.z, p1);
    p1 = fmaf(fmaxf(c.u1.w + vb1.w, 0.f), c.w21.w, p1);

    float z0 = p0 + __shfl_xor_sync(0xffffffffu, p0, 16);
    float z1 = p1 + __shfl_xor_sync(0xffffffffu, p1, 16);
    float s  = (c.lane & 16) ? z1 : z0;
    s += __shfl_xor_sync(0xffffffffu, s, 8);
    s += __shfl_xor_sync(0xffffffffu, s, 4);
    s += __shfl_xor_sync(0xffffffffu, s, 2);
    s += __shfl_xor_sync(0xffffffffu, s, 1);
    if (c.lane == 0)
        c.outp[gi] = s + c.bc;
    else if (c.lane == 16)
        c.outp[gi + 1] = s + c.bc;
}

__global__ void __launch_bounds__(512) combine_kernel(
    const float* __restrict__ expW2, float* __restrict__ pred)
{
    extern __shared__ float4 sV[];       // GT*128 float4 = 72KB
    const int g0   = blockIdx.x * GT;
    const int warp = threadIdx.x >> 5;
    const int lane = threadIdx.x & 31;
    const int b    = blockIdx.y * 16 + warp;
    const int nG   = (G_ - g0) < GT ? (G_ - g0) : GT;   // 36 or 6 (even)

    const float4* V4 = reinterpret_cast<const float4*>(d_V);
    for (int i = threadIdx.x; i < nG * 128; i += blockDim.x)
        sV[i] = V4[g0 * 128 + i];
    __syncthreads();

#if __CUDA_ARCH__ >= 900
    cudaGridDependencySynchronize();     // wait for stageDE outputs
#endif

    const int   e0  = d_eidx[2 * b], e1 = d_eidx[2 * b + 1];
    const float gw0 = d_gw[2 * b],   gw1 = d_gw[2 * b + 1];

    const float4* U4 = reinterpret_cast<const float4*>(d_U) + b * 128;
    const float4* W4 = reinterpret_cast<const float4*>(expW2);

    CombCtx c;
    c.lane = lane;
    c.bc   = d_biasc[b];
    c.outp = pred + b * G_ + g0;
    c.sVbase0 = sV + e0 * 32 + lane;
    c.sVbase1 = sV + e1 * 32 + lane;
    c.u0 = U4[e0 * 32 + lane];
    c.u1 = U4[e1 * 32 + lane];
    float4 w20 = W4[e0 * 32 + lane];
    w20.x *= gw0; w20.y *= gw0; w20.z *= gw0; w20.w *= gw0;
    float4 w21 = W4[e1 * 32 + lane];
    w21.x *= gw1; w21.y *= gw1; w21.z *= gw1; w21.w *= gw1;
    c.w20 = w20; c.w21 = w21;

    if (nG == GT) {
#pragma unroll
        for (int gi = 0; gi < GT; gi += 2)
            comb_pair(c, gi);
    } else {
#pragma unroll
        for (int gi = 0; gi < 6; gi += 2)     // tail tile: nG = 6
            comb_pair(c, gi);
    }
}

// =========================================================
extern "C" void kernel_launch(void* const* d_in, const int* in_sizes, int n_in,
                              void* d_out, int out_size)
{
    const float* drug_atom = (const float*)d_in[0];
    const float* gex       = (const float*)d_in[1];
    const float* idose     = (const float*)d_in[2];
    const float* cW1 = (const float*)d_in[3];  const float* cb1 = (const float*)d_in[4];
    const float* cW2 = (const float*)d_in[5];  const float* cb2 = (const float*)d_in[6];
    const float* cW3 = (const float*)d_in[7];  const float* cb3 = (const float*)d_in[8];
    const float* dW1 = (const float*)d_in[9];  const float* db1 = (const float*)d_in[10];
    const float* dW2 = (const float*)d_in[11]; const float* db2 = (const float*)d_in[12];
    const float* gene_emb = (const float*)d_in[13];
    const float* gW1 = (const float*)d_in[14]; const float* gb1 = (const float*)d_in[15];
    const float* gW2 = (const float*)d_in[16]; const float* gb2 = (const float*)d_in[17];
    const float* eW1 = (const float*)d_in[18]; const float* eb1 = (const float*)d_in[19];
    const float* eW2 = (const float*)d_in[20]; const float* eb2 = (const float*)d_in[21];

    float* pred = (float*)d_out;
    float* cellOut = (out_size >= B_ * G_ + B_ * DCELL) ? pred + B_ * G_ : nullptr;

    stageA<<<704, 256>>>(drug_atom, gex, cW1, idose, dW1, db1, dW2, db2);
    stageBC<<<252, 256>>>(cb1, cW2, cb2, cW3, cb3, gene_emb, eW1, cellOut);
    stageDE<<<384, 256>>>(gW1, gb1, gW2, gb2, eW1, eb1, eb2);

    const size_t csmem = (size_t)GT * 128 * sizeof(float4);   // 73728 B
    cudaFuncSetAttribute(combine_kernel,
                         cudaFuncAttributeMaxDynamicSharedMemorySize, (int)csmem);
    {
        cudaLaunchConfig_t cfg = {};
        cfg.gridDim  = dim3((G_ + GT - 1) / GT, B_ / 16, 1);
        cfg.blockDim = dim3(512, 1, 1);
        cfg.dynamicSmemBytes = csmem;
        cfg.stream = 0;
        cudaLaunchAttribute attrs[1];
        attrs[0].id = cudaLaunchAttributeProgrammaticStreamSerialization;
        attrs[0].val.programmaticStreamSerializationAllowed = 1;
        cfg.attrs = attrs;
        cfg.numAttrs = 1;
        cudaLaunchKernelEx(&cfg, combine_kernel, eW2, pred);
    }
}